// round 11
// baseline (speedup 1.0000x reference)
#include <cuda_runtime.h>
#include <cuda_fp16.h>
#include <cstdint>
#include <cstring>

#define T_SEQ 2048
#define D_MODEL 1024
#define NH 16
#define HD 64
#define BATCH 4
#define M_TOT (BATCH * T_SEQ)       // 8192
#define N_QKV (3 * D_MODEL)         // 3072

// ---------------- scratch (__device__ globals: allocation-free) -------------
__device__ __half g_qkvh[(size_t)M_TOT * N_QKV];        // 48 MB, fp16 qkv
__device__ __half g_xh[(size_t)M_TOT * D_MODEL];
__device__ __half g_wq[(size_t)N_QKV * D_MODEL];
__device__ __half g_wo[(size_t)D_MODEL * D_MODEL];
__device__ __half g_ah[(size_t)M_TOT * D_MODEL];

// ---------------- helpers ---------------------------------------------------
__device__ __forceinline__ uint32_t smem_u32(const void* p) {
    uint32_t a;
    asm("{ .reg .u64 t; cvta.to.shared.u64 t, %1; cvt.u32.u64 %0, t; }"
        : "=r"(a) : "l"(p));
    return a;
}
__device__ __forceinline__ void cp_async16(uint32_t smem_dst, const void* gmem_src) {
    asm volatile("cp.async.cg.shared.global [%0], [%1], 16;"
                 :: "r"(smem_dst), "l"(gmem_src) : "memory");
}
__device__ __forceinline__ void cp_commit() {
    asm volatile("cp.async.commit_group;" ::: "memory");
}
__device__ __forceinline__ void cp_wait1() {
    asm volatile("cp.async.wait_group 1;" ::: "memory");
}
__device__ __forceinline__ void ldsm_x4(uint32_t addr, uint32_t& r0, uint32_t& r1,
                                        uint32_t& r2, uint32_t& r3) {
    asm volatile("ldmatrix.sync.aligned.m8n8.x4.shared.b16 {%0,%1,%2,%3}, [%4];"
                 : "=r"(r0), "=r"(r1), "=r"(r2), "=r"(r3) : "r"(addr));
}
__device__ __forceinline__ void mma_f16(float* d, const uint32_t* a, const uint32_t* b) {
    asm volatile(
        "mma.sync.aligned.m16n8k16.row.col.f32.f16.f16.f32 "
        "{%0,%1,%2,%3}, {%4,%5,%6,%7}, {%8,%9}, {%0,%1,%2,%3};"
        : "+f"(d[0]), "+f"(d[1]), "+f"(d[2]), "+f"(d[3])
        : "r"(a[0]), "r"(a[1]), "r"(a[2]), "r"(a[3]), "r"(b[0]), "r"(b[1]));
}

// ---------------- fused fp32 -> fp16 convert (x, Wqkv, Wout in one grid) -----
#define NX4 ((M_TOT * D_MODEL) / 4)
#define NWQ4 ((N_QKV * D_MODEL) / 4)
#define NWO4 ((D_MODEL * D_MODEL) / 4)

__global__ __launch_bounds__(256) void conv_all(
    const float* __restrict__ x, const float* __restrict__ wq_in,
    const float* __restrict__ wo_in,
    __half* __restrict__ xh, __half* __restrict__ wqh, __half* __restrict__ woh)
{
    int i = blockIdx.x * blockDim.x + threadIdx.x;
    const float* src; __half* dst; int j;
    if (i < NX4)                       { src = x;     dst = xh;  j = i; }
    else if (i < NX4 + NWQ4)           { src = wq_in; dst = wqh; j = i - NX4; }
    else if (i < NX4 + NWQ4 + NWO4)    { src = wo_in; dst = woh; j = i - NX4 - NWQ4; }
    else return;
    float4 v = ((const float4*)src)[j];
    __half h[4] = {__float2half_rn(v.x), __float2half_rn(v.y),
                   __float2half_rn(v.z), __float2half_rn(v.w)};
    *(uint2*)(dst + 4 * (size_t)j) = *(uint2*)h;
}

// ---------------- HMMA GEMM: C = A @ B^T + bias (OT = float | __half) --------
// CTA 128x128, 4 warps (2x2), warp tile 64x64 -> halves per-SM ldsm traffic
// (the smem port was co-saturating with the tensor pipe at 8 warps).
// KC=64, 3-stage cp.async, one __syncthreads per chunk. 144 B padded rows.
#define KC 64
#define LDROW 144
#define TILE_B (128 * LDROW)         // 18432
#define STAGE_B (2 * TILE_B)         // 36864
#define SMEM_BYTES (3 * STAGE_B)     // 110592 (epilogue needs 67584 < this)
#define NCHUNK (1024 / KC)           // 16

template <typename OT>
__global__ __launch_bounds__(128) void gemm_hmma(
    const __half* __restrict__ A, const __half* __restrict__ Bw,
    const float* __restrict__ bias, OT* __restrict__ C, int N)
{
    extern __shared__ char smem[];
    const int tid  = threadIdx.x;
    const int wid  = tid >> 5, lane = tid & 31;
    const int wm   = wid >> 1, wn = wid & 1;       // 2 x 2 warps, 64x64 each
    const int bn   = blockIdx.x * 128, bm = blockIdx.y * 128;
    const uint32_t sbase = smem_u32(smem);

    const char* gsrc[2];
    gsrc[0] = (const char*)A  + (size_t)bm * 2048;
    gsrc[1] = (const char*)Bw + (size_t)bn * 2048;

    // loader closed form (128 threads, 2048 cp.async16 per stage -> 16 each):
    // c16 = (tid&7)*16 fixed; row = (tid>>3) + (i&7)*16; which = i>>3
    const int lc16 = (tid & 7) * 16;
    const int brow = tid >> 3;

    auto load_stage = [&](int chunk, int slot) {
        const size_t k0b = (size_t)chunk * (KC * 2);
        uint32_t sdst = sbase + slot * STAGE_B;
        #pragma unroll
        for (int i = 0; i < 16; i++) {
            const int which = i >> 3;
            const int row   = brow + (i & 7) * 16;
            cp_async16(sdst + which * TILE_B + row * LDROW + lc16,
                       gsrc[which] + (size_t)row * 2048 + k0b + lc16);
        }
    };

    float acc[4][8][4];
    #pragma unroll
    for (int mt = 0; mt < 4; mt++)
        #pragma unroll
        for (int nt = 0; nt < 8; nt++)
            #pragma unroll
            for (int j = 0; j < 4; j++) acc[mt][nt][j] = 0.f;

    const uint32_t a_off = (uint32_t)(wm * 64 + (lane & 15)) * LDROW + (lane >> 4) * 16;
    const uint32_t b_off = (uint32_t)(wn * 64 + ((lane >> 4) & 1) * 8 + (lane & 7)) * LDROW
                         + ((lane >> 3) & 1) * 16;

    load_stage(0, 0); cp_commit();
    load_stage(1, 1); cp_commit();

    for (int c = 0; c < NCHUNK; c++) {
        const int slot = c % 3;
        cp_wait1();                       // chunk c resident
        __syncthreads();                  // everyone done with slot (c+2)%3
        if (c + 2 < NCHUNK) load_stage(c + 2, (c + 2) % 3);
        cp_commit();                      // uniform group accounting

        const uint32_t st = sbase + slot * STAGE_B;
        const uint32_t tA = st, tB = st + TILE_B;

        #pragma unroll
        for (int ks = 0; ks < 4; ks++) {
            const uint32_t kb = ks * 32;
            uint32_t aa[4][4], bb[4][4];
            #pragma unroll
            for (int mt = 0; mt < 4; mt++)
                ldsm_x4(tA + a_off + (uint32_t)mt * 16 * LDROW + kb,
                        aa[mt][0], aa[mt][1], aa[mt][2], aa[mt][3]);
            #pragma unroll
            for (int p = 0; p < 4; p++)
                ldsm_x4(tB + b_off + (uint32_t)p * 16 * LDROW + kb,
                        bb[p][0], bb[p][1], bb[p][2], bb[p][3]);
            #pragma unroll
            for (int mt = 0; mt < 4; mt++)
                #pragma unroll
                for (int nt = 0; nt < 8; nt++)
                    mma_f16(acc[mt][nt], aa[mt], &bb[nt >> 1][(nt & 1) * 2]);
        }
    }
    __syncthreads();                      // all compute done before smem reuse

    // epilogue: stage -> coalesced float4 stores + bias
    float* stage = (float*)smem;          // [128][132]
    #pragma unroll
    for (int mt = 0; mt < 4; mt++)
        #pragma unroll
        for (int nt = 0; nt < 8; nt++) {
            int row = wm * 64 + mt * 16 + (lane >> 2);
            int col = wn * 64 + nt * 8 + (lane & 3) * 2;
            stage[row * 132 + col]           = acc[mt][nt][0];
            stage[row * 132 + col + 1]       = acc[mt][nt][1];
            stage[(row + 8) * 132 + col]     = acc[mt][nt][2];
            stage[(row + 8) * 132 + col + 1] = acc[mt][nt][3];
        }
    __syncthreads();

    #pragma unroll
    for (int i = 0; i < 32; i++) {
        int idx = tid + i * 128;          // 0..4095
        int row = idx >> 5;
        int c4  = (idx & 31) * 4;
        float4 bv = *(const float4*)(bias + bn + c4);
        float ox = stage[row * 132 + c4 + 0] + bv.x;
        float oy = stage[row * 132 + c4 + 1] + bv.y;
        float oz = stage[row * 132 + c4 + 2] + bv.z;
        float ow = stage[row * 132 + c4 + 3] + bv.w;
        if constexpr (sizeof(OT) == 4) {
            float4 o = {ox, oy, oz, ow};
            *(float4*)((float*)C + (size_t)(bm + row) * N + bn + c4) = o;
        } else {
            __half h4[4] = {__float2half_rn(ox), __float2half_rn(oy),
                            __float2half_rn(oz), __float2half_rn(ow)};
            *(uint2*)((__half*)C + (size_t)(bm + row) * N + bn + c4) = *(uint2*)h4;
        }
    }
}

// ---------------- local windowed attention (unchanged from R9/R10) -----------
#define QT 32
#define KT 96
#define KTV 100
#define KPH 72
#define QPF 68
#define ATTN_SMEM (96 * KPH * 2 + KTV * KPH * 2 + QT * QPF * 4 + 8 * 80 * 4)

__global__ __launch_bounds__(256) void attn_local(
    const __half* __restrict__ qkv, __half* __restrict__ outh)
{
    extern __shared__ char asmem[];
    __half* Ks = (__half*)asmem;                    // [96][72]
    __half* Vs = Ks + 96 * KPH;                     // [100][72] interleaved
    float*  Qs = (float*)(Vs + KTV * KPH);          // [32][68] pre-scaled
    float*  Ps = Qs + QT * QPF;                     // [8][80]

    const int b = blockIdx.z, h = blockIdx.y;
    const int t0 = blockIdx.x * QT;
    const int kbase = t0 - 32;
    const int tid = threadIdx.x;

    #pragma unroll
    for (int i = 0; i < 6; i++) {
        int idx = tid + i * 256;                    // 0..1535
        if (idx < 768) {
            int row = idx >> 3, c = idx & 7;
            int tk = kbase + row;
            uint4 v = {0u, 0u, 0u, 0u};
            if (tk >= 0 && tk < T_SEQ)
                v = ((const uint4*)(qkv + ((size_t)(b * T_SEQ + tk)) * N_QKV
                                    + D_MODEL + h * HD))[c];
            *(uint4*)(Ks + row * KPH + c * 8) = v;
        } else if (idx < 1152) {
            int j = idx - 768;
            int row = j >> 2, c = j & 3;
            int tk = kbase + row;
            uint4 lo = {0u, 0u, 0u, 0u}, hi = {0u, 0u, 0u, 0u};
            if (tk >= 0 && tk < T_SEQ) {
                const __half* base = qkv + ((size_t)(b * T_SEQ + tk)) * N_QKV
                                   + 2 * D_MODEL + h * HD;
                lo = ((const uint4*)base)[c];
                hi = ((const uint4*)(base + 32))[c];
            }
            __half lh[8], hh[8], oo[16];
            memcpy(lh, &lo, 16); memcpy(hh, &hi, 16);
            #pragma unroll
            for (int k = 0; k < 8; k++) { oo[2 * k] = lh[k]; oo[2 * k + 1] = hh[k]; }
            uint4 o0, o1;
            memcpy(&o0, oo, 16); memcpy(&o1, oo + 8, 16);
            __half* dst = Vs + row * KPH + c * 16;
            ((uint4*)dst)[0] = o0; ((uint4*)dst)[1] = o1;
        } else if (idx < 1408) {
            int j = idx - 1152;
            int row = j >> 3, c = j & 7;
            uint4 v = ((const uint4*)(qkv + ((size_t)(b * T_SEQ + t0 + row)) * N_QKV
                                      + h * HD))[c];
            __half qh[8]; memcpy(qh, &v, 16);
            float* dst = Qs + row * QPF + c * 8;
            #pragma unroll
            for (int k = 0; k < 8; k++) dst[k] = __half2float(qh[k]) * 0.125f;
        }
    }
    if (tid < 36) {
        int r = tid / 9, c = tid % 9;
        *(uint4*)(Vs + (96 + r) * KPH + c * 8) = make_uint4(0, 0, 0, 0);
    }
    __syncthreads();

    const int warp = tid >> 5, lane = tid & 31;
    const int g  = lane >> 3;
    const int kq = lane & 7;

    #pragma unroll 1
    for (int qq = 0; qq < 4; qq++) {
        const int qi = warp * 4 + qq;
        const int t  = t0 + qi;

        const bool v0 = (t - 32 + lane) >= 0;
        const bool v1 = (t + lane) < T_SEQ;
        float d0 = 0.f, d1 = 0.f;
        const uint4* k0p = (const uint4*)(Ks + (qi + lane) * KPH);
        const uint4* k1p = (const uint4*)(Ks + (qi + 32 + lane) * KPH);
        const float4* qf = (const float4*)(Qs + qi * QPF);
        #pragma unroll
        for (int i = 0; i < 8; i++) {
            uint4 ka = k0p[i], kb = k1p[i];
            float4 qa = qf[2 * i], qb = qf[2 * i + 1];
            const __half2* pa = (const __half2*)&ka;
            const __half2* pb = (const __half2*)&kb;
            float2 a0 = __half22float2(pa[0]), a1 = __half22float2(pa[1]);
            float2 a2 = __half22float2(pa[2]), a3 = __half22float2(pa[3]);
            float2 b0 = __half22float2(pb[0]), b1 = __half22float2(pb[1]);
            float2 b2 = __half22float2(pb[2]), b3 = __half22float2(pb[3]);
            d0 = fmaf(qa.x, a0.x, d0); d0 = fmaf(qa.y, a0.y, d0);
            d0 = fmaf(qa.z, a1.x, d0); d0 = fmaf(qa.w, a1.y, d0);
            d0 = fmaf(qb.x, a2.x, d0); d0 = fmaf(qb.y, a2.y, d0);
            d0 = fmaf(qb.z, a3.x, d0); d0 = fmaf(qb.w, a3.y, d0);
            d1 = fmaf(qa.x, b0.x, d1); d1 = fmaf(qa.y, b0.y, d1);
            d1 = fmaf(qa.z, b1.x, d1); d1 = fmaf(qa.w, b1.y, d1);
            d1 = fmaf(qb.x, b2.x, d1); d1 = fmaf(qb.y, b2.y, d1);
            d1 = fmaf(qb.z, b3.x, d1); d1 = fmaf(qb.w, b3.y, d1);
        }
        float s0 = v0 ? d0 : -1e30f;
        float s1 = v1 ? d1 : -1e30f;

        float part = Qs[qi * QPF + lane]      * __half2float(Ks[(qi + 64) * KPH + lane])
                   + Qs[qi * QPF + lane + 32] * __half2float(Ks[(qi + 64) * KPH + lane + 32]);
        part += __shfl_xor_sync(0xffffffffu, part, 16);
        part += __shfl_xor_sync(0xffffffffu, part, 8);
        part += __shfl_xor_sync(0xffffffffu, part, 4);
        part += __shfl_xor_sync(0xffffffffu, part, 2);
        part += __shfl_xor_sync(0xffffffffu, part, 1);
        const bool v2 = (t + 32) < T_SEQ;
        float s2 = (lane == 0 && v2) ? part : -1e30f;

        float m = fmaxf(fmaxf(s0, s1), s2);
        m = fmaxf(m, __shfl_xor_sync(0xffffffffu, m, 16));
        m = fmaxf(m, __shfl_xor_sync(0xffffffffu, m, 8));
        m = fmaxf(m, __shfl_xor_sync(0xffffffffu, m, 4));
        m = fmaxf(m, __shfl_xor_sync(0xffffffffu, m, 2));
        m = fmaxf(m, __shfl_xor_sync(0xffffffffu, m, 1));
        float p0 = __expf(s0 - m);
        float p1 = __expf(s1 - m);
        float p2 = __expf(s2 - m);
        float l = p0 + p1 + p2;
        l += __shfl_xor_sync(0xffffffffu, l, 16);
        l += __shfl_xor_sync(0xffffffffu, l, 8);
        l += __shfl_xor_sync(0xffffffffu, l, 4);
        l += __shfl_xor_sync(0xffffffffu, l, 2);
        l += __shfl_xor_sync(0xffffffffu, l, 1);
        float inv = 1.f / l;

        float* pw = &Ps[warp * 80];
        pw[lane]      = p0 * inv;
        pw[lane + 32] = p1 * inv;
        if (lane < 4) pw[64 + lane] = (lane == 0) ? p2 * inv : 0.f;
        __syncwarp();

        float av[8];
        #pragma unroll
        for (int i = 0; i < 8; i++) av[i] = 0.f;
        const __half* vq = Vs + (qi + g) * KPH + kq * 8;
        #pragma unroll
        for (int jb = 0; jb < 17; jb++) {
            float p = pw[jb * 4 + g];
            uint4 v = *(const uint4*)(vq + jb * 4 * KPH);
            const __half2* ph = (const __half2*)&v;
            float2 f0 = __half22float2(ph[0]);
            float2 f1 = __half22float2(ph[1]);
            float2 f2 = __half22float2(ph[2]);
            float2 f3 = __half22float2(ph[3]);
            av[0] = fmaf(p, f0.x, av[0]); av[4] = fmaf(p, f0.y, av[4]);
            av[1] = fmaf(p, f1.x, av[1]); av[5] = fmaf(p, f1.y, av[5]);
            av[2] = fmaf(p, f2.x, av[2]); av[6] = fmaf(p, f2.y, av[6]);
            av[3] = fmaf(p, f3.x, av[3]); av[7] = fmaf(p, f3.y, av[7]);
        }
        #pragma unroll
        for (int i = 0; i < 8; i++) {
            av[i] += __shfl_xor_sync(0xffffffffu, av[i], 8);
            av[i] += __shfl_xor_sync(0xffffffffu, av[i], 16);
        }

        size_t off = ((size_t)(b * T_SEQ + t)) * D_MODEL + h * HD;
        if (g == 0) {
            __half h4[4] = {__float2half_rn(av[0]), __float2half_rn(av[1]),
                            __float2half_rn(av[2]), __float2half_rn(av[3])};
            *(uint2*)(outh + off + kq * 4) = *(uint2*)h4;
        } else if (g == 2) {
            __half h4[4] = {__float2half_rn(av[4]), __float2half_rn(av[5]),
                            __float2half_rn(av[6]), __float2half_rn(av[7])};
            *(uint2*)(outh + off + 32 + kq * 4) = *(uint2*)h4;
        }
        __syncwarp();
    }
}

// ---------------------------------------------------------------------------
extern "C" void kernel_launch(void* const* d_in, const int* in_sizes, int n_in,
                              void* d_out, int out_size)
{
    const float* x    = (const float*)d_in[0];
    const float* Wqkv = (const float*)d_in[1];
    const float* bqkv = (const float*)d_in[2];
    const float* Wout = (const float*)d_in[3];
    const float* bout = (const float*)d_in[4];
    float* out = (float*)d_out;

    __half *qkvh, *xh, *wq, *wo, *ah;
    cudaGetSymbolAddress((void**)&qkvh, g_qkvh);
    cudaGetSymbolAddress((void**)&xh, g_xh);
    cudaGetSymbolAddress((void**)&wq, g_wq);
    cudaGetSymbolAddress((void**)&wo, g_wo);
    cudaGetSymbolAddress((void**)&ah, g_ah);

    cudaFuncSetAttribute(gemm_hmma<__half>, cudaFuncAttributeMaxDynamicSharedMemorySize, SMEM_BYTES);
    cudaFuncSetAttribute(gemm_hmma<float>,  cudaFuncAttributeMaxDynamicSharedMemorySize, SMEM_BYTES);
    cudaFuncSetAttribute(attn_local, cudaFuncAttributeMaxDynamicSharedMemorySize, ATTN_SMEM);

    {
        int total = NX4 + NWQ4 + NWO4;
        conv_all<<<(total + 255) / 256, 256>>>(x, Wqkv, Wout, xh, wq, wo);
    }

    gemm_hmma<__half><<<dim3(N_QKV / 128, M_TOT / 128), 128, SMEM_BYTES>>>(
        xh, wq, bqkv, qkvh, N_QKV);

    attn_local<<<dim3(T_SEQ / QT, NH, BATCH), 256, ATTN_SMEM>>>(qkvh, ah);

    gemm_hmma<float><<<dim3(D_MODEL / 128, M_TOT / 128), 128, SMEM_BYTES>>>(
        ah, wo, bout, out, D_MODEL);
}

// round 12
// speedup vs baseline: 1.2776x; 1.2776x over previous
#include <cuda_runtime.h>
#include <cuda_fp16.h>
#include <cstdint>
#include <cstring>

#define T_SEQ 2048
#define D_MODEL 1024
#define NH 16
#define HD 64
#define BATCH 4
#define M_TOT (BATCH * T_SEQ)       // 8192
#define N_QKV (3 * D_MODEL)         // 3072

// ---------------- scratch (__device__ globals: allocation-free) -------------
__device__ __half g_qkvh[(size_t)M_TOT * N_QKV];        // 48 MB, fp16 qkv
__device__ __half g_xh[(size_t)M_TOT * D_MODEL];
__device__ __half g_wq[(size_t)N_QKV * D_MODEL];
__device__ __half g_wo[(size_t)D_MODEL * D_MODEL];
__device__ __half g_ah[(size_t)M_TOT * D_MODEL];

// ---------------- helpers ---------------------------------------------------
__device__ __forceinline__ uint32_t smem_u32(const void* p) {
    uint32_t a;
    asm("{ .reg .u64 t; cvta.to.shared.u64 t, %1; cvt.u32.u64 %0, t; }"
        : "=r"(a) : "l"(p));
    return a;
}
__device__ __forceinline__ void cp_async16(uint32_t smem_dst, const void* gmem_src) {
    asm volatile("cp.async.cg.shared.global [%0], [%1], 16;"
                 :: "r"(smem_dst), "l"(gmem_src) : "memory");
}
__device__ __forceinline__ void cp_commit() {
    asm volatile("cp.async.commit_group;" ::: "memory");
}
__device__ __forceinline__ void cp_wait1() {
    asm volatile("cp.async.wait_group 1;" ::: "memory");
}
__device__ __forceinline__ void ldsm_x4(uint32_t addr, uint32_t& r0, uint32_t& r1,
                                        uint32_t& r2, uint32_t& r3) {
    asm volatile("ldmatrix.sync.aligned.m8n8.x4.shared.b16 {%0,%1,%2,%3}, [%4];"
                 : "=r"(r0), "=r"(r1), "=r"(r2), "=r"(r3) : "r"(addr));
}
__device__ __forceinline__ void mma_f16(float* d, const uint32_t* a, const uint32_t* b) {
    asm volatile(
        "mma.sync.aligned.m16n8k16.row.col.f32.f16.f16.f32 "
        "{%0,%1,%2,%3}, {%4,%5,%6,%7}, {%8,%9}, {%0,%1,%2,%3};"
        : "+f"(d[0]), "+f"(d[1]), "+f"(d[2]), "+f"(d[3])
        : "r"(a[0]), "r"(a[1]), "r"(a[2]), "r"(a[3]), "r"(b[0]), "r"(b[1]));
}

// ---------------- fused fp32 -> fp16 convert ---------------------------------
#define NX4 ((M_TOT * D_MODEL) / 4)
#define NWQ4 ((N_QKV * D_MODEL) / 4)
#define NWO4 ((D_MODEL * D_MODEL) / 4)

__global__ __launch_bounds__(256) void conv_all(
    const float* __restrict__ x, const float* __restrict__ wq_in,
    const float* __restrict__ wo_in,
    __half* __restrict__ xh, __half* __restrict__ wqh, __half* __restrict__ woh)
{
    int i = blockIdx.x * blockDim.x + threadIdx.x;
    const float* src; __half* dst; int j;
    if (i < NX4)                       { src = x;     dst = xh;  j = i; }
    else if (i < NX4 + NWQ4)           { src = wq_in; dst = wqh; j = i - NX4; }
    else if (i < NX4 + NWQ4 + NWO4)    { src = wo_in; dst = woh; j = i - NX4 - NWQ4; }
    else return;
    float4 v = ((const float4*)src)[j];
    __half h[4] = {__float2half_rn(v.x), __float2half_rn(v.y),
                   __float2half_rn(v.z), __float2half_rn(v.w)};
    *(uint2*)(dst + 4 * (size_t)j) = *(uint2*)h;
}

// ---------------- HMMA GEMM (reverted to R9 best config) ---------------------
#define KC 64
#define LDROW 144
#define TILE_B (128 * LDROW)
#define STAGE_B (2 * TILE_B)
#define SMEM_BYTES (3 * STAGE_B)     // 110592
#define NCHUNK (1024 / KC)

template <typename OT>
__global__ __launch_bounds__(256, 2) void gemm_hmma(
    const __half* __restrict__ A, const __half* __restrict__ Bw,
    const float* __restrict__ bias, OT* __restrict__ C, int N)
{
    extern __shared__ char smem[];
    const int tid  = threadIdx.x;
    const int wid  = tid >> 5, lane = tid & 31;
    const int wm   = wid >> 1, wn = wid & 1;
    const int bn   = blockIdx.x * 128, bm = blockIdx.y * 128;
    const uint32_t sbase = smem_u32(smem);

    const char* gsrc[2];
    gsrc[0] = (const char*)A  + (size_t)bm * 2048;
    gsrc[1] = (const char*)Bw + (size_t)bn * 2048;

    int ld_which[8], ld_row[8], ld_c16[8];
    #pragma unroll
    for (int i = 0; i < 8; i++) {
        int idx = tid + i * 256;
        ld_which[i] = idx >> 10;
        ld_row[i]   = (idx >> 3) & 127;
        ld_c16[i]   = idx & 7;
    }

    auto load_stage = [&](int chunk, int slot) {
        const size_t k0b = (size_t)chunk * (KC * 2);
        uint32_t sdst = sbase + slot * STAGE_B;
        #pragma unroll
        for (int i = 0; i < 8; i++) {
            const char* g = gsrc[ld_which[i]] + (size_t)ld_row[i] * 2048 + k0b + ld_c16[i] * 16;
            uint32_t s = sdst + ld_which[i] * TILE_B + ld_row[i] * LDROW + ld_c16[i] * 16;
            cp_async16(s, g);
        }
    };

    float acc[2][8][4];
    #pragma unroll
    for (int mt = 0; mt < 2; mt++)
        #pragma unroll
        for (int nt = 0; nt < 8; nt++)
            #pragma unroll
            for (int j = 0; j < 4; j++) acc[mt][nt][j] = 0.f;

    const uint32_t a_off = (uint32_t)(wm * 32 + (lane & 15)) * LDROW + (lane >> 4) * 16;
    const uint32_t b_off = (uint32_t)(wn * 64 + ((lane >> 4) & 1) * 8 + (lane & 7)) * LDROW
                         + ((lane >> 3) & 1) * 16;

    load_stage(0, 0); cp_commit();
    load_stage(1, 1); cp_commit();

    uint32_t aa[2][2][4], bb[2][4][4];

    for (int c = 0; c < NCHUNK; c++) {
        const int slot = c % 3;
        cp_wait1();
        __syncthreads();
        if (c + 2 < NCHUNK) load_stage(c + 2, (c + 2) % 3);
        cp_commit();

        const uint32_t st = sbase + slot * STAGE_B;
        const uint32_t tA = st, tB = st + TILE_B;

        #pragma unroll
        for (int mt = 0; mt < 2; mt++)
            ldsm_x4(tA + a_off + (uint32_t)mt * 16 * LDROW,
                    aa[0][mt][0], aa[0][mt][1], aa[0][mt][2], aa[0][mt][3]);
        #pragma unroll
        for (int p = 0; p < 4; p++)
            ldsm_x4(tB + b_off + (uint32_t)p * 16 * LDROW,
                    bb[0][p][0], bb[0][p][1], bb[0][p][2], bb[0][p][3]);

        #pragma unroll
        for (int ks = 0; ks < 4; ks++) {
            const int cur = ks & 1, nxt = cur ^ 1;
            if (ks < 3) {
                const uint32_t kb = (ks + 1) * 32;
                #pragma unroll
                for (int mt = 0; mt < 2; mt++)
                    ldsm_x4(tA + a_off + (uint32_t)mt * 16 * LDROW + kb,
                            aa[nxt][mt][0], aa[nxt][mt][1], aa[nxt][mt][2], aa[nxt][mt][3]);
                #pragma unroll
                for (int p = 0; p < 4; p++)
                    ldsm_x4(tB + b_off + (uint32_t)p * 16 * LDROW + kb,
                            bb[nxt][p][0], bb[nxt][p][1], bb[nxt][p][2], bb[nxt][p][3]);
            }
            #pragma unroll
            for (int mt = 0; mt < 2; mt++)
                #pragma unroll
                for (int nt = 0; nt < 8; nt++)
                    mma_f16(acc[mt][nt], aa[cur][mt], &bb[cur][nt >> 1][(nt & 1) * 2]);
        }
    }
    __syncthreads();

    float* stage = (float*)smem;          // [128][132]
    #pragma unroll
    for (int mt = 0; mt < 2; mt++)
        #pragma unroll
        for (int nt = 0; nt < 8; nt++) {
            int row = wm * 32 + mt * 16 + (lane >> 2);
            int col = wn * 64 + nt * 8 + (lane & 3) * 2;
            stage[row * 132 + col]           = acc[mt][nt][0];
            stage[row * 132 + col + 1]       = acc[mt][nt][1];
            stage[(row + 8) * 132 + col]     = acc[mt][nt][2];
            stage[(row + 8) * 132 + col + 1] = acc[mt][nt][3];
        }
    __syncthreads();

    #pragma unroll
    for (int i = 0; i < 16; i++) {
        int idx = tid + i * 256;
        int row = idx >> 5;
        int c4  = (idx & 31) * 4;
        float4 bv = *(const float4*)(bias + bn + c4);
        float ox = stage[row * 132 + c4 + 0] + bv.x;
        float oy = stage[row * 132 + c4 + 1] + bv.y;
        float oz = stage[row * 132 + c4 + 2] + bv.z;
        float ow = stage[row * 132 + c4 + 3] + bv.w;
        if constexpr (sizeof(OT) == 4) {
            float4 o = {ox, oy, oz, ow};
            *(float4*)((float*)C + (size_t)(bm + row) * N + bn + c4) = o;
        } else {
            __half h4[4] = {__float2half_rn(ox), __float2half_rn(oy),
                            __float2half_rn(oz), __float2half_rn(ow)};
            *(uint2*)((__half*)C + (size_t)(bm + row) * N + bn + c4) = *(uint2*)h4;
        }
    }
}

// ---------------- tensor-core local attention --------------------------------
// CTA = (b, h, 32-query tile), 128 threads (4 warps).
// S(32x96) = Q@K^T via mma (warps 0-2, 32 keys each); softmax with 2 smem
// reduction rounds; P fp16 through smem; O = P@V via mma (warps split dims).
// Q/K stride 144 B (GEMM recipe); Ps/Vt stride 208 B.
#define SQK_B 144
#define SPV_B 208
#define AOFF_Q 0
#define AOFF_K (32 * SQK_B)                     // 4608
#define AOFF_V (AOFF_K + 96 * SQK_B)            // 18432  (Vt: [64 dims][104 keys])
#define AOFF_P (AOFF_V + 64 * SPV_B)            // 31744  (Ps: [32 rows][104 keys])
#define AOFF_MX (AOFF_P + 32 * SPV_B)           // 38400
#define AOFF_SM (AOFF_MX + 512)                 // 38912
#define ATTN_SMEM (AOFF_SM + 512)               // 39424

__global__ __launch_bounds__(128) void attn_mma(
    const __half* __restrict__ qkv, __half* __restrict__ outh)
{
    extern __shared__ char asmem[];
    __half* Qs = (__half*)(asmem + AOFF_Q);     // [32][72]
    __half* Ks = (__half*)(asmem + AOFF_K);     // [96][72]
    __half* Vt = (__half*)(asmem + AOFF_V);     // [64][104] (dim-major)
    __half* Ps = (__half*)(asmem + AOFF_P);     // [32][104]
    float* maxp = (float*)(asmem + AOFF_MX);    // [32][4]
    float* sump = (float*)(asmem + AOFF_SM);    // [32][4]

    const int b = blockIdx.z, h = blockIdx.y;
    const int t0 = blockIdx.x * 32;
    const int kbase = t0 - 32;
    const int tid = threadIdx.x;
    const int w = tid >> 5, lane = tid & 31;
    const uint32_t sb = smem_u32(asmem);

    // ---- staging ----
    const __half2 qscale = __float2half2_rn(0.125f);
    #pragma unroll
    for (int i = tid; i < 256; i += 128) {       // Q (pre-scaled)
        int row = i >> 3, c = i & 7;
        uint4 v = ((const uint4*)(qkv + ((size_t)(b * T_SEQ + t0 + row)) * N_QKV
                                  + h * HD))[c];
        __half2 hv[4]; memcpy(hv, &v, 16);
        #pragma unroll
        for (int k = 0; k < 4; k++) hv[k] = __hmul2(hv[k], qscale);
        memcpy(&v, hv, 16);
        *(uint4*)((char*)Qs + row * SQK_B + c * 16) = v;
    }
    #pragma unroll
    for (int i = tid; i < 768; i += 128) {       // K
        int row = i >> 3, c = i & 7;
        int tk = kbase + row;
        uint4 v = {0u, 0u, 0u, 0u};
        if (tk >= 0 && tk < T_SEQ)
            v = ((const uint4*)(qkv + ((size_t)(b * T_SEQ + tk)) * N_QKV
                                + D_MODEL + h * HD))[c];
        *(uint4*)((char*)Ks + row * SQK_B + c * 16) = v;
    }
    #pragma unroll
    for (int i = tid; i < 768; i += 128) {       // V transposed -> Vt[dim][key]
        int row = i >> 3, c = i & 7;
        int tk = kbase + row;
        uint4 v = {0u, 0u, 0u, 0u};
        if (tk >= 0 && tk < T_SEQ)
            v = ((const uint4*)(qkv + ((size_t)(b * T_SEQ + tk)) * N_QKV
                                + 2 * D_MODEL + h * HD))[c];
        __half hv[8]; memcpy(hv, &v, 16);
        #pragma unroll
        for (int d = 0; d < 8; d++)
            *(__half*)((char*)Vt + (c * 8 + d) * SPV_B + row * 2) = hv[d];
    }
    __syncthreads();

    // ---- S = Q @ K^T (warps 0-2, 32 keys each) ----
    float sc[2][4][4];
    #pragma unroll
    for (int mt = 0; mt < 2; mt++)
        #pragma unroll
        for (int nt = 0; nt < 4; nt++)
            #pragma unroll
            for (int c = 0; c < 4; c++) sc[mt][nt][c] = 0.f;

    const uint32_t a_off = (uint32_t)(lane & 15) * SQK_B + (lane >> 4) * 16;
    const uint32_t b_off = (uint32_t)(((lane >> 4) & 1) * 8 + (lane & 7)) * SQK_B
                         + ((lane >> 3) & 1) * 16;

    if (w < 3) {
        const uint32_t Qb = sb + AOFF_Q;
        const uint32_t Kb = sb + AOFF_K + (uint32_t)w * 32 * SQK_B;
        #pragma unroll
        for (int ks = 0; ks < 4; ks++) {
            const uint32_t kb = ks * 32;
            uint32_t qa[2][4], kb4[2][4];
            #pragma unroll
            for (int mt = 0; mt < 2; mt++)
                ldsm_x4(Qb + a_off + (uint32_t)mt * 16 * SQK_B + kb,
                        qa[mt][0], qa[mt][1], qa[mt][2], qa[mt][3]);
            #pragma unroll
            for (int p = 0; p < 2; p++)
                ldsm_x4(Kb + b_off + (uint32_t)p * 16 * SQK_B + kb,
                        kb4[p][0], kb4[p][1], kb4[p][2], kb4[p][3]);
            #pragma unroll
            for (int mt = 0; mt < 2; mt++)
                #pragma unroll
                for (int nt = 0; nt < 4; nt++)
                    mma_f16(sc[mt][nt], qa[mt], &kb4[nt >> 1][(nt & 1) * 2]);
        }
    }

    // ---- mask + row max (rows ri: row = (ri>>1)*16 + (ri&1)*8 + lane>>2) ----
    float rmax[4] = {-1e30f, -1e30f, -1e30f, -1e30f};
    if (w < 3) {
        #pragma unroll
        for (int mt = 0; mt < 2; mt++)
            #pragma unroll
            for (int nt = 0; nt < 4; nt++) {
                int j0 = w * 32 + nt * 8 + ((lane & 3) << 1);
                #pragma unroll
                for (int c = 0; c < 4; c++) {
                    int j = j0 + (c & 1);
                    int row = mt * 16 + (c >> 1) * 8 + (lane >> 2);
                    int key = kbase + j;
                    bool ok = (j >= row) && (j <= row + 64) && (key >= 0) && (key < T_SEQ);
                    float s = ok ? sc[mt][nt][c] : -1e30f;
                    sc[mt][nt][c] = s;
                    int ri = mt * 2 + (c >> 1);
                    rmax[ri] = fmaxf(rmax[ri], s);
                }
            }
        #pragma unroll
        for (int ri = 0; ri < 4; ri++) {
            rmax[ri] = fmaxf(rmax[ri], __shfl_xor_sync(0xffffffffu, rmax[ri], 1));
            rmax[ri] = fmaxf(rmax[ri], __shfl_xor_sync(0xffffffffu, rmax[ri], 2));
        }
        if ((lane & 3) == 0)
            #pragma unroll
            for (int ri = 0; ri < 4; ri++) {
                int row = (ri >> 1) * 16 + (ri & 1) * 8 + (lane >> 2);
                maxp[row * 4 + w] = rmax[ri];
            }
    } else {
        if ((lane & 3) == 0)
            #pragma unroll
            for (int ri = 0; ri < 4; ri++) {
                int row = (ri >> 1) * 16 + (ri & 1) * 8 + (lane >> 2);
                maxp[row * 4 + 3] = -1e30f;
                sump[row * 4 + 3] = 0.f;
            }
    }
    __syncthreads();

    // ---- exp + row sums ----
    float gmx[4], rsum[4] = {0.f, 0.f, 0.f, 0.f};
    #pragma unroll
    for (int ri = 0; ri < 4; ri++) {
        int row = (ri >> 1) * 16 + (ri & 1) * 8 + (lane >> 2);
        float4 mp = *(const float4*)&maxp[row * 4];
        gmx[ri] = fmaxf(fmaxf(mp.x, mp.y), fmaxf(mp.z, mp.w));
    }
    if (w < 3) {
        #pragma unroll
        for (int mt = 0; mt < 2; mt++)
            #pragma unroll
            for (int nt = 0; nt < 4; nt++)
                #pragma unroll
                for (int c = 0; c < 4; c++) {
                    int ri = mt * 2 + (c >> 1);
                    float e = __expf(sc[mt][nt][c] - gmx[ri]);
                    sc[mt][nt][c] = e;
                    rsum[ri] += e;
                }
        #pragma unroll
        for (int ri = 0; ri < 4; ri++) {
            rsum[ri] += __shfl_xor_sync(0xffffffffu, rsum[ri], 1);
            rsum[ri] += __shfl_xor_sync(0xffffffffu, rsum[ri], 2);
        }
        if ((lane & 3) == 0)
            #pragma unroll
            for (int ri = 0; ri < 4; ri++) {
                int row = (ri >> 1) * 16 + (ri & 1) * 8 + (lane >> 2);
                sump[row * 4 + w] = rsum[ri];
            }
    }
    __syncthreads();

    // ---- normalize, write P fp16 ----
    if (w < 3) {
        float inv[4];
        #pragma unroll
        for (int ri = 0; ri < 4; ri++) {
            int row = (ri >> 1) * 16 + (ri & 1) * 8 + (lane >> 2);
            float4 sp = *(const float4*)&sump[row * 4];
            inv[ri] = 1.f / (sp.x + sp.y + sp.z + sp.w);
        }
        #pragma unroll
        for (int mt = 0; mt < 2; mt++)
            #pragma unroll
            for (int nt = 0; nt < 4; nt++) {
                int j0 = w * 32 + nt * 8 + ((lane & 3) << 1);
                int rowA = mt * 16 + (lane >> 2);
                __half2 pA = __floats2half2_rn(sc[mt][nt][0] * inv[mt * 2],
                                               sc[mt][nt][1] * inv[mt * 2]);
                __half2 pB = __floats2half2_rn(sc[mt][nt][2] * inv[mt * 2 + 1],
                                               sc[mt][nt][3] * inv[mt * 2 + 1]);
                *(__half2*)((char*)Ps + rowA * SPV_B + j0 * 2) = pA;
                *(__half2*)((char*)Ps + (rowA + 8) * SPV_B + j0 * 2) = pB;
            }
    }
    __syncthreads();

    // ---- O = P @ V (all 4 warps, 16 dims each, 6 k-steps over 96 keys) ----
    float oc[2][2][4];
    #pragma unroll
    for (int mt = 0; mt < 2; mt++)
        #pragma unroll
        for (int nt = 0; nt < 2; nt++)
            #pragma unroll
            for (int c = 0; c < 4; c++) oc[mt][nt][c] = 0.f;

    const uint32_t Pb = sb + AOFF_P;
    const uint32_t Vb = sb + AOFF_V + (uint32_t)w * 16 * SPV_B;
    const uint32_t a_offP = (uint32_t)(lane & 15) * SPV_B + (lane >> 4) * 16;
    const uint32_t b_offV = (uint32_t)(((lane >> 4) & 1) * 8 + (lane & 7)) * SPV_B
                          + ((lane >> 3) & 1) * 16;

    #pragma unroll
    for (int ks = 0; ks < 6; ks++) {
        const uint32_t kb = ks * 32;
        uint32_t pa[2][4], vb[4];
        #pragma unroll
        for (int mt = 0; mt < 2; mt++)
            ldsm_x4(Pb + a_offP + (uint32_t)mt * 16 * SPV_B + kb,
                    pa[mt][0], pa[mt][1], pa[mt][2], pa[mt][3]);
        ldsm_x4(Vb + b_offV + kb, vb[0], vb[1], vb[2], vb[3]);
        #pragma unroll
        for (int mt = 0; mt < 2; mt++)
            #pragma unroll
            for (int nt = 0; nt < 2; nt++)
                mma_f16(oc[mt][nt], pa[mt], &vb[nt * 2]);
    }

    // ---- write O ----
    const size_t base = ((size_t)(b * T_SEQ + t0)) * D_MODEL + h * HD;
    #pragma unroll
    for (int mt = 0; mt < 2; mt++)
        #pragma unroll
        for (int nt = 0; nt < 2; nt++) {
            int rowA = mt * 16 + (lane >> 2);
            int col = w * 16 + nt * 8 + ((lane & 3) << 1);
            __half2 hA = __floats2half2_rn(oc[mt][nt][0], oc[mt][nt][1]);
            __half2 hB = __floats2half2_rn(oc[mt][nt][2], oc[mt][nt][3]);
            *(__half2*)(outh + base + (size_t)rowA * D_MODEL + col) = hA;
            *(__half2*)(outh + base + (size_t)(rowA + 8) * D_MODEL + col) = hB;
        }
}

// ---------------------------------------------------------------------------
extern "C" void kernel_launch(void* const* d_in, const int* in_sizes, int n_in,
                              void* d_out, int out_size)
{
    const float* x    = (const float*)d_in[0];
    const float* Wqkv = (const float*)d_in[1];
    const float* bqkv = (const float*)d_in[2];
    const float* Wout = (const float*)d_in[3];
    const float* bout = (const float*)d_in[4];
    float* out = (float*)d_out;

    __half *qkvh, *xh, *wq, *wo, *ah;
    cudaGetSymbolAddress((void**)&qkvh, g_qkvh);
    cudaGetSymbolAddress((void**)&xh, g_xh);
    cudaGetSymbolAddress((void**)&wq, g_wq);
    cudaGetSymbolAddress((void**)&wo, g_wo);
    cudaGetSymbolAddress((void**)&ah, g_ah);

    cudaFuncSetAttribute(gemm_hmma<__half>, cudaFuncAttributeMaxDynamicSharedMemorySize, SMEM_BYTES);
    cudaFuncSetAttribute(gemm_hmma<float>,  cudaFuncAttributeMaxDynamicSharedMemorySize, SMEM_BYTES);
    cudaFuncSetAttribute(attn_mma, cudaFuncAttributeMaxDynamicSharedMemorySize, ATTN_SMEM);

    {
        int total = NX4 + NWQ4 + NWO4;
        conv_all<<<(total + 255) / 256, 256>>>(x, Wqkv, Wout, xh, wq, wo);
    }

    gemm_hmma<__half><<<dim3(N_QKV / 128, M_TOT / 128), 256, SMEM_BYTES>>>(
        xh, wq, bqkv, qkvh, N_QKV);

    attn_mma<<<dim3(T_SEQ / 32, NH, BATCH), 128, ATTN_SMEM>>>(qkvh, ah);

    gemm_hmma<float><<<dim3(D_MODEL / 128, M_TOT / 128), 256, SMEM_BYTES>>>(
        ah, wo, bout, out, D_MODEL);
}

// round 13
// speedup vs baseline: 1.2850x; 1.0058x over previous
#include <cuda_runtime.h>
#include <cuda_fp16.h>
#include <cstdint>
#include <cstring>

#define T_SEQ 2048
#define D_MODEL 1024
#define NH 16
#define HD 64
#define BATCH 4
#define M_TOT (BATCH * T_SEQ)       // 8192
#define N_QKV (3 * D_MODEL)         // 3072
#define M_HALF (M_TOT / 2)          // 4096

// ---------------- scratch (__device__ globals: allocation-free) -------------
__device__ __half g_qkvh[(size_t)M_TOT * N_QKV];        // 48 MB, fp16 qkv
__device__ __half g_xh[(size_t)M_TOT * D_MODEL];
__device__ __half g_wq[(size_t)N_QKV * D_MODEL];
__device__ __half g_wo[(size_t)D_MODEL * D_MODEL];
__device__ __half g_ah[(size_t)M_TOT * D_MODEL];

// ---------------- helpers ---------------------------------------------------
__device__ __forceinline__ uint32_t smem_u32(const void* p) {
    uint32_t a;
    asm("{ .reg .u64 t; cvta.to.shared.u64 t, %1; cvt.u32.u64 %0, t; }"
        : "=r"(a) : "l"(p));
    return a;
}
__device__ __forceinline__ void cp_async16(uint32_t smem_dst, const void* gmem_src) {
    asm volatile("cp.async.cg.shared.global [%0], [%1], 16;"
                 :: "r"(smem_dst), "l"(gmem_src) : "memory");
}
__device__ __forceinline__ void cp_commit() {
    asm volatile("cp.async.commit_group;" ::: "memory");
}
__device__ __forceinline__ void cp_wait1() {
    asm volatile("cp.async.wait_group 1;" ::: "memory");
}
__device__ __forceinline__ void ldsm_x4(uint32_t addr, uint32_t& r0, uint32_t& r1,
                                        uint32_t& r2, uint32_t& r3) {
    asm volatile("ldmatrix.sync.aligned.m8n8.x4.shared.b16 {%0,%1,%2,%3}, [%4];"
                 : "=r"(r0), "=r"(r1), "=r"(r2), "=r"(r3) : "r"(addr));
}
__device__ __forceinline__ void mma_f16(float* d, const uint32_t* a, const uint32_t* b) {
    asm volatile(
        "mma.sync.aligned.m16n8k16.row.col.f32.f16.f16.f32 "
        "{%0,%1,%2,%3}, {%4,%5,%6,%7}, {%8,%9}, {%0,%1,%2,%3};"
        : "+f"(d[0]), "+f"(d[1]), "+f"(d[2]), "+f"(d[3])
        : "r"(a[0]), "r"(a[1]), "r"(a[2]), "r"(a[3]), "r"(b[0]), "r"(b[1]));
}

// ---------------- fused fp32 -> fp16 convert ---------------------------------
#define NX4 ((M_TOT * D_MODEL) / 4)
#define NWQ4 ((N_QKV * D_MODEL) / 4)
#define NWO4 ((D_MODEL * D_MODEL) / 4)

__global__ __launch_bounds__(256) void conv_all(
    const float* __restrict__ x, const float* __restrict__ wq_in,
    const float* __restrict__ wo_in,
    __half* __restrict__ xh, __half* __restrict__ wqh, __half* __restrict__ woh)
{
    int i = blockIdx.x * blockDim.x + threadIdx.x;
    const float* src; __half* dst; int j;
    if (i < NX4)                       { src = x;     dst = xh;  j = i; }
    else if (i < NX4 + NWQ4)           { src = wq_in; dst = wqh; j = i - NX4; }
    else if (i < NX4 + NWQ4 + NWO4)    { src = wo_in; dst = woh; j = i - NX4 - NWQ4; }
    else return;
    float4 v = ((const float4*)src)[j];
    __half h[4] = {__float2half_rn(v.x), __float2half_rn(v.y),
                   __float2half_rn(v.z), __float2half_rn(v.w)};
    *(uint2*)(dst + 4 * (size_t)j) = *(uint2*)h;
}

// ---------------- HMMA GEMM (R9/R11 best config, unchanged) ------------------
#define KC 64
#define LDROW 144
#define TILE_B (128 * LDROW)
#define STAGE_B (2 * TILE_B)
#define SMEM_BYTES (3 * STAGE_B)     // 110592
#define NCHUNK (1024 / KC)

template <typename OT>
__global__ __launch_bounds__(256, 2) void gemm_hmma(
    const __half* __restrict__ A, const __half* __restrict__ Bw,
    const float* __restrict__ bias, OT* __restrict__ C, int N)
{
    extern __shared__ char smem[];
    const int tid  = threadIdx.x;
    const int wid  = tid >> 5, lane = tid & 31;
    const int wm   = wid >> 1, wn = wid & 1;
    const int bn   = blockIdx.x * 128, bm = blockIdx.y * 128;
    const uint32_t sbase = smem_u32(smem);

    const char* gsrc[2];
    gsrc[0] = (const char*)A  + (size_t)bm * 2048;
    gsrc[1] = (const char*)Bw + (size_t)bn * 2048;

    int ld_which[8], ld_row[8], ld_c16[8];
    #pragma unroll
    for (int i = 0; i < 8; i++) {
        int idx = tid + i * 256;
        ld_which[i] = idx >> 10;
        ld_row[i]   = (idx >> 3) & 127;
        ld_c16[i]   = idx & 7;
    }

    auto load_stage = [&](int chunk, int slot) {
        const size_t k0b = (size_t)chunk * (KC * 2);
        uint32_t sdst = sbase + slot * STAGE_B;
        #pragma unroll
        for (int i = 0; i < 8; i++) {
            const char* g = gsrc[ld_which[i]] + (size_t)ld_row[i] * 2048 + k0b + ld_c16[i] * 16;
            uint32_t s = sdst + ld_which[i] * TILE_B + ld_row[i] * LDROW + ld_c16[i] * 16;
            cp_async16(s, g);
        }
    };

    float acc[2][8][4];
    #pragma unroll
    for (int mt = 0; mt < 2; mt++)
        #pragma unroll
        for (int nt = 0; nt < 8; nt++)
            #pragma unroll
            for (int j = 0; j < 4; j++) acc[mt][nt][j] = 0.f;

    const uint32_t a_off = (uint32_t)(wm * 32 + (lane & 15)) * LDROW + (lane >> 4) * 16;
    const uint32_t b_off = (uint32_t)(wn * 64 + ((lane >> 4) & 1) * 8 + (lane & 7)) * LDROW
                         + ((lane >> 3) & 1) * 16;

    load_stage(0, 0); cp_commit();
    load_stage(1, 1); cp_commit();

    uint32_t aa[2][2][4], bb[2][4][4];

    for (int c = 0; c < NCHUNK; c++) {
        const int slot = c % 3;
        cp_wait1();
        __syncthreads();
        if (c + 2 < NCHUNK) load_stage(c + 2, (c + 2) % 3);
        cp_commit();

        const uint32_t st = sbase + slot * STAGE_B;
        const uint32_t tA = st, tB = st + TILE_B;

        #pragma unroll
        for (int mt = 0; mt < 2; mt++)
            ldsm_x4(tA + a_off + (uint32_t)mt * 16 * LDROW,
                    aa[0][mt][0], aa[0][mt][1], aa[0][mt][2], aa[0][mt][3]);
        #pragma unroll
        for (int p = 0; p < 4; p++)
            ldsm_x4(tB + b_off + (uint32_t)p * 16 * LDROW,
                    bb[0][p][0], bb[0][p][1], bb[0][p][2], bb[0][p][3]);

        #pragma unroll
        for (int ks = 0; ks < 4; ks++) {
            const int cur = ks & 1, nxt = cur ^ 1;
            if (ks < 3) {
                const uint32_t kb = (ks + 1) * 32;
                #pragma unroll
                for (int mt = 0; mt < 2; mt++)
                    ldsm_x4(tA + a_off + (uint32_t)mt * 16 * LDROW + kb,
                            aa[nxt][mt][0], aa[nxt][mt][1], aa[nxt][mt][2], aa[nxt][mt][3]);
                #pragma unroll
                for (int p = 0; p < 4; p++)
                    ldsm_x4(tB + b_off + (uint32_t)p * 16 * LDROW + kb,
                            bb[nxt][p][0], bb[nxt][p][1], bb[nxt][p][2], bb[nxt][p][3]);
            }
            #pragma unroll
            for (int mt = 0; mt < 2; mt++)
                #pragma unroll
                for (int nt = 0; nt < 8; nt++)
                    mma_f16(acc[mt][nt], aa[cur][mt], &bb[cur][nt >> 1][(nt & 1) * 2]);
        }
    }
    __syncthreads();

    float* stage = (float*)smem;          // [128][132]
    #pragma unroll
    for (int mt = 0; mt < 2; mt++)
        #pragma unroll
        for (int nt = 0; nt < 8; nt++) {
            int row = wm * 32 + mt * 16 + (lane >> 2);
            int col = wn * 64 + nt * 8 + (lane & 3) * 2;
            stage[row * 132 + col]           = acc[mt][nt][0];
            stage[row * 132 + col + 1]       = acc[mt][nt][1];
            stage[(row + 8) * 132 + col]     = acc[mt][nt][2];
            stage[(row + 8) * 132 + col + 1] = acc[mt][nt][3];
        }
    __syncthreads();

    #pragma unroll
    for (int i = 0; i < 16; i++) {
        int idx = tid + i * 256;
        int row = idx >> 5;
        int c4  = (idx & 31) * 4;
        float4 bv = *(const float4*)(bias + bn + c4);
        float ox = stage[row * 132 + c4 + 0] + bv.x;
        float oy = stage[row * 132 + c4 + 1] + bv.y;
        float oz = stage[row * 132 + c4 + 2] + bv.z;
        float ow = stage[row * 132 + c4 + 3] + bv.w;
        if constexpr (sizeof(OT) == 4) {
            float4 o = {ox, oy, oz, ow};
            *(float4*)((float*)C + (size_t)(bm + row) * N + bn + c4) = o;
        } else {
            __half h4[4] = {__float2half_rn(ox), __float2half_rn(oy),
                            __float2half_rn(oz), __float2half_rn(ow)};
            *(uint2*)((__half*)C + (size_t)(bm + row) * N + bn + c4) = *(uint2*)h4;
        }
    }
}

// ---------------- tensor-core local attention (R11, unchanged) ---------------
#define SQK_B 144
#define SPV_B 208
#define AOFF_Q 0
#define AOFF_K (32 * SQK_B)
#define AOFF_V (AOFF_K + 96 * SQK_B)
#define AOFF_P (AOFF_V + 64 * SPV_B)
#define AOFF_MX (AOFF_P + 32 * SPV_B)
#define AOFF_SM (AOFF_MX + 512)
#define ATTN_SMEM (AOFF_SM + 512)

__global__ __launch_bounds__(128) void attn_mma(
    const __half* __restrict__ qkv, __half* __restrict__ outh)
{
    extern __shared__ char asmem[];
    __half* Qs = (__half*)(asmem + AOFF_Q);
    __half* Ks = (__half*)(asmem + AOFF_K);
    __half* Vt = (__half*)(asmem + AOFF_V);
    __half* Ps = (__half*)(asmem + AOFF_P);
    float* maxp = (float*)(asmem + AOFF_MX);
    float* sump = (float*)(asmem + AOFF_SM);

    const int b = blockIdx.z, h = blockIdx.y;
    const int t0 = blockIdx.x * 32;
    const int kbase = t0 - 32;
    const int tid = threadIdx.x;
    const int w = tid >> 5, lane = tid & 31;
    const uint32_t sb = smem_u32(asmem);

    const __half2 qscale = __float2half2_rn(0.125f);
    #pragma unroll
    for (int i = tid; i < 256; i += 128) {
        int row = i >> 3, c = i & 7;
        uint4 v = ((const uint4*)(qkv + ((size_t)(b * T_SEQ + t0 + row)) * N_QKV
                                  + h * HD))[c];
        __half2 hv[4]; memcpy(hv, &v, 16);
        #pragma unroll
        for (int k = 0; k < 4; k++) hv[k] = __hmul2(hv[k], qscale);
        memcpy(&v, hv, 16);
        *(uint4*)((char*)Qs + row * SQK_B + c * 16) = v;
    }
    #pragma unroll
    for (int i = tid; i < 768; i += 128) {
        int row = i >> 3, c = i & 7;
        int tk = kbase + row;
        uint4 v = {0u, 0u, 0u, 0u};
        if (tk >= 0 && tk < T_SEQ)
            v = ((const uint4*)(qkv + ((size_t)(b * T_SEQ + tk)) * N_QKV
                                + D_MODEL + h * HD))[c];
        *(uint4*)((char*)Ks + row * SQK_B + c * 16) = v;
    }
    #pragma unroll
    for (int i = tid; i < 768; i += 128) {
        int row = i >> 3, c = i & 7;
        int tk = kbase + row;
        uint4 v = {0u, 0u, 0u, 0u};
        if (tk >= 0 && tk < T_SEQ)
            v = ((const uint4*)(qkv + ((size_t)(b * T_SEQ + tk)) * N_QKV
                                + 2 * D_MODEL + h * HD))[c];
        __half hv[8]; memcpy(hv, &v, 16);
        #pragma unroll
        for (int d = 0; d < 8; d++)
            *(__half*)((char*)Vt + (c * 8 + d) * SPV_B + row * 2) = hv[d];
    }
    __syncthreads();

    float sc[2][4][4];
    #pragma unroll
    for (int mt = 0; mt < 2; mt++)
        #pragma unroll
        for (int nt = 0; nt < 4; nt++)
            #pragma unroll
            for (int c = 0; c < 4; c++) sc[mt][nt][c] = 0.f;

    const uint32_t a_off = (uint32_t)(lane & 15) * SQK_B + (lane >> 4) * 16;
    const uint32_t b_off = (uint32_t)(((lane >> 4) & 1) * 8 + (lane & 7)) * SQK_B
                         + ((lane >> 3) & 1) * 16;

    if (w < 3) {
        const uint32_t Qb = sb + AOFF_Q;
        const uint32_t Kb = sb + AOFF_K + (uint32_t)w * 32 * SQK_B;
        #pragma unroll
        for (int ks = 0; ks < 4; ks++) {
            const uint32_t kb = ks * 32;
            uint32_t qa[2][4], kb4[2][4];
            #pragma unroll
            for (int mt = 0; mt < 2; mt++)
                ldsm_x4(Qb + a_off + (uint32_t)mt * 16 * SQK_B + kb,
                        qa[mt][0], qa[mt][1], qa[mt][2], qa[mt][3]);
            #pragma unroll
            for (int p = 0; p < 2; p++)
                ldsm_x4(Kb + b_off + (uint32_t)p * 16 * SQK_B + kb,
                        kb4[p][0], kb4[p][1], kb4[p][2], kb4[p][3]);
            #pragma unroll
            for (int mt = 0; mt < 2; mt++)
                #pragma unroll
                for (int nt = 0; nt < 4; nt++)
                    mma_f16(sc[mt][nt], qa[mt], &kb4[nt >> 1][(nt & 1) * 2]);
        }
    }

    float rmax[4] = {-1e30f, -1e30f, -1e30f, -1e30f};
    if (w < 3) {
        #pragma unroll
        for (int mt = 0; mt < 2; mt++)
            #pragma unroll
            for (int nt = 0; nt < 4; nt++) {
                int j0 = w * 32 + nt * 8 + ((lane & 3) << 1);
                #pragma unroll
                for (int c = 0; c < 4; c++) {
                    int j = j0 + (c & 1);
                    int row = mt * 16 + (c >> 1) * 8 + (lane >> 2);
                    int key = kbase + j;
                    bool ok = (j >= row) && (j <= row + 64) && (key >= 0) && (key < T_SEQ);
                    float s = ok ? sc[mt][nt][c] : -1e30f;
                    sc[mt][nt][c] = s;
                    int ri = mt * 2 + (c >> 1);
                    rmax[ri] = fmaxf(rmax[ri], s);
                }
            }
        #pragma unroll
        for (int ri = 0; ri < 4; ri++) {
            rmax[ri] = fmaxf(rmax[ri], __shfl_xor_sync(0xffffffffu, rmax[ri], 1));
            rmax[ri] = fmaxf(rmax[ri], __shfl_xor_sync(0xffffffffu, rmax[ri], 2));
        }
        if ((lane & 3) == 0)
            #pragma unroll
            for (int ri = 0; ri < 4; ri++) {
                int row = (ri >> 1) * 16 + (ri & 1) * 8 + (lane >> 2);
                maxp[row * 4 + w] = rmax[ri];
            }
    } else {
        if ((lane & 3) == 0)
            #pragma unroll
            for (int ri = 0; ri < 4; ri++) {
                int row = (ri >> 1) * 16 + (ri & 1) * 8 + (lane >> 2);
                maxp[row * 4 + 3] = -1e30f;
                sump[row * 4 + 3] = 0.f;
            }
    }
    __syncthreads();

    float gmx[4], rsum[4] = {0.f, 0.f, 0.f, 0.f};
    #pragma unroll
    for (int ri = 0; ri < 4; ri++) {
        int row = (ri >> 1) * 16 + (ri & 1) * 8 + (lane >> 2);
        float4 mp = *(const float4*)&maxp[row * 4];
        gmx[ri] = fmaxf(fmaxf(mp.x, mp.y), fmaxf(mp.z, mp.w));
    }
    if (w < 3) {
        #pragma unroll
        for (int mt = 0; mt < 2; mt++)
            #pragma unroll
            for (int nt = 0; nt < 4; nt++)
                #pragma unroll
                for (int c = 0; c < 4; c++) {
                    int ri = mt * 2 + (c >> 1);
                    float e = __expf(sc[mt][nt][c] - gmx[ri]);
                    sc[mt][nt][c] = e;
                    rsum[ri] += e;
                }
        #pragma unroll
        for (int ri = 0; ri < 4; ri++) {
            rsum[ri] += __shfl_xor_sync(0xffffffffu, rsum[ri], 1);
            rsum[ri] += __shfl_xor_sync(0xffffffffu, rsum[ri], 2);
        }
        if ((lane & 3) == 0)
            #pragma unroll
            for (int ri = 0; ri < 4; ri++) {
                int row = (ri >> 1) * 16 + (ri & 1) * 8 + (lane >> 2);
                sump[row * 4 + w] = rsum[ri];
            }
    }
    __syncthreads();

    if (w < 3) {
        float inv[4];
        #pragma unroll
        for (int ri = 0; ri < 4; ri++) {
            int row = (ri >> 1) * 16 + (ri & 1) * 8 + (lane >> 2);
            float4 sp = *(const float4*)&sump[row * 4];
            inv[ri] = 1.f / (sp.x + sp.y + sp.z + sp.w);
        }
        #pragma unroll
        for (int mt = 0; mt < 2; mt++)
            #pragma unroll
            for (int nt = 0; nt < 4; nt++) {
                int j0 = w * 32 + nt * 8 + ((lane & 3) << 1);
                int rowA = mt * 16 + (lane >> 2);
                __half2 pA = __floats2half2_rn(sc[mt][nt][0] * inv[mt * 2],
                                               sc[mt][nt][1] * inv[mt * 2]);
                __half2 pB = __floats2half2_rn(sc[mt][nt][2] * inv[mt * 2 + 1],
                                               sc[mt][nt][3] * inv[mt * 2 + 1]);
                *(__half2*)((char*)Ps + rowA * SPV_B + j0 * 2) = pA;
                *(__half2*)((char*)Ps + (rowA + 8) * SPV_B + j0 * 2) = pB;
            }
    }
    __syncthreads();

    float oc[2][2][4];
    #pragma unroll
    for (int mt = 0; mt < 2; mt++)
        #pragma unroll
        for (int nt = 0; nt < 2; nt++)
            #pragma unroll
            for (int c = 0; c < 4; c++) oc[mt][nt][c] = 0.f;

    const uint32_t Pb = sb + AOFF_P;
    const uint32_t Vb = sb + AOFF_V + (uint32_t)w * 16 * SPV_B;
    const uint32_t a_offP = (uint32_t)(lane & 15) * SPV_B + (lane >> 4) * 16;
    const uint32_t b_offV = (uint32_t)(((lane >> 4) & 1) * 8 + (lane & 7)) * SPV_B
                          + ((lane >> 3) & 1) * 16;

    #pragma unroll
    for (int ks = 0; ks < 6; ks++) {
        const uint32_t kb = ks * 32;
        uint32_t pa[2][4], vb[4];
        #pragma unroll
        for (int mt = 0; mt < 2; mt++)
            ldsm_x4(Pb + a_offP + (uint32_t)mt * 16 * SPV_B + kb,
                    pa[mt][0], pa[mt][1], pa[mt][2], pa[mt][3]);
        ldsm_x4(Vb + b_offV + kb, vb[0], vb[1], vb[2], vb[3]);
        #pragma unroll
        for (int mt = 0; mt < 2; mt++)
            #pragma unroll
            for (int nt = 0; nt < 2; nt++)
                mma_f16(oc[mt][nt], pa[mt], &vb[nt * 2]);
    }

    const size_t base = ((size_t)(b * T_SEQ + t0)) * D_MODEL + h * HD;
    #pragma unroll
    for (int mt = 0; mt < 2; mt++)
        #pragma unroll
        for (int nt = 0; nt < 2; nt++) {
            int rowA = mt * 16 + (lane >> 2);
            int col = w * 16 + nt * 8 + ((lane & 3) << 1);
            __half2 hA = __floats2half2_rn(oc[mt][nt][0], oc[mt][nt][1]);
            __half2 hB = __floats2half2_rn(oc[mt][nt][2], oc[mt][nt][3]);
            *(__half2*)(outh + base + (size_t)rowA * D_MODEL + col) = hA;
            *(__half2*)(outh + base + (size_t)(rowA + 8) * D_MODEL + col) = hB;
        }
}

// ---------------------------------------------------------------------------
// Two-stream pipelined schedule, split by batch halves (attention is
// batch-local, so the split is exact). s1 forks off the capture (default)
// stream via events and joins back before return.
extern "C" void kernel_launch(void* const* d_in, const int* in_sizes, int n_in,
                              void* d_out, int out_size)
{
    const float* x    = (const float*)d_in[0];
    const float* Wqkv = (const float*)d_in[1];
    const float* bqkv = (const float*)d_in[2];
    const float* Wout = (const float*)d_in[3];
    const float* bout = (const float*)d_in[4];
    float* out = (float*)d_out;

    __half *qkvh, *xh, *wq, *wo, *ah;
    cudaGetSymbolAddress((void**)&qkvh, g_qkvh);
    cudaGetSymbolAddress((void**)&xh, g_xh);
    cudaGetSymbolAddress((void**)&wq, g_wq);
    cudaGetSymbolAddress((void**)&wo, g_wo);
    cudaGetSymbolAddress((void**)&ah, g_ah);

    cudaFuncSetAttribute(gemm_hmma<__half>, cudaFuncAttributeMaxDynamicSharedMemorySize, SMEM_BYTES);
    cudaFuncSetAttribute(gemm_hmma<float>,  cudaFuncAttributeMaxDynamicSharedMemorySize, SMEM_BYTES);
    cudaFuncSetAttribute(attn_mma, cudaFuncAttributeMaxDynamicSharedMemorySize, ATTN_SMEM);

    // one-time side stream + fork/join events (no device-memory APIs involved)
    static cudaStream_t s1 = nullptr;
    static cudaEvent_t evA = nullptr, evDone = nullptr;
    if (s1 == nullptr) {
        cudaStreamCreateWithFlags(&s1, cudaStreamNonBlocking);
        cudaEventCreateWithFlags(&evA, cudaEventDisableTiming);
        cudaEventCreateWithFlags(&evDone, cudaEventDisableTiming);
    }

    // s0 = default (capture) stream
    {
        int total = NX4 + NWQ4 + NWO4;
        conv_all<<<(total + 255) / 256, 256>>>(x, Wqkv, Wout, xh, wq, wo);
    }

    // QKV half A (rows 0..4095)
    gemm_hmma<__half><<<dim3(N_QKV / 128, M_HALF / 128), 256, SMEM_BYTES>>>(
        xh, wq, bqkv, qkvh, N_QKV);
    cudaEventRecord(evA, 0);

    // s1: attention + out-proj for half A, overlapped with s0's half-B QKV
    cudaStreamWaitEvent(s1, evA, 0);
    attn_mma<<<dim3(T_SEQ / 32, NH, BATCH / 2), 128, ATTN_SMEM, s1>>>(qkvh, ah);
    gemm_hmma<float><<<dim3(D_MODEL / 128, M_HALF / 128), 256, SMEM_BYTES, s1>>>(
        ah, wo, bout, out, D_MODEL);
    cudaEventRecord(evDone, s1);

    // s0: QKV half B, then its attention + out-proj
    gemm_hmma<__half><<<dim3(N_QKV / 128, M_HALF / 128), 256, SMEM_BYTES>>>(
        xh + (size_t)M_HALF * D_MODEL, wq, bqkv,
        qkvh + (size_t)M_HALF * N_QKV, N_QKV);
    attn_mma<<<dim3(T_SEQ / 32, NH, BATCH / 2), 128, ATTN_SMEM>>>(
        qkvh + (size_t)M_HALF * N_QKV, ah + (size_t)M_HALF * D_MODEL);
    gemm_hmma<float><<<dim3(D_MODEL / 128, M_HALF / 128), 256, SMEM_BYTES>>>(
        ah + (size_t)M_HALF * D_MODEL, wo, bout,
        out + (size_t)M_HALF * D_MODEL, D_MODEL);

    // join s1 back into the capture stream
    cudaStreamWaitEvent(0, evDone, 0);
}